// round 4
// baseline (speedup 1.0000x reference)
#include <cuda_runtime.h>
#include <cuda_bf16.h>
#include <stdint.h>

// GCN mean aggregation:
//   out[i, :] = mean over {nodes[i]} ∪ neigh_idx[i, 0..K-1] of features[idx, :]
// features [V=100000, D=128] f32, nodes [B] int{32|64}, neigh [B,32] int{32|64}.
//
// One warp per node; lane = one float4 slice (32x16B = full 512B row).
// L2 is the binding resource:
//  - feature loads: L2::evict_last policy (table reused ~16.5x, keep resident)
//  - index loads / output stores: streaming (.cs)
//  - indices via ONE coalesced 256B load + shfl broadcast
//  - 4 independent accumulator chains + 64-reg budget so ptxas front-batches
//    ~8-10 LDG.128s per warp (raise in-flight loads to saturate LTS).

static constexpr int D4 = 32;    // 128 floats = 32 float4/row
static constexpr int KN = 32;
static constexpr float INV_CNT = 1.0f / 33.0f;

__device__ int g_idx_is64;

__global__ void detect_idx_dtype(const int* __restrict__ p) {
    // little-endian int64 values < 2^31 have all odd 32-bit words zero
    int all0 = 1;
#pragma unroll
    for (int i = 0; i < 64; i++) all0 &= (p[2 * i + 1] == 0);
    g_idx_is64 = all0;
}

__device__ __forceinline__ uint64_t make_keep_policy() {
    uint64_t pol;
    asm("createpolicy.fractional.L2::evict_last.b64 %0, 1.0;" : "=l"(pol));
    return pol;
}

__device__ __forceinline__ float4 ldg_keep(const float4* p, uint64_t pol) {
    float4 v;
    asm volatile("ld.global.nc.L2::cache_hint.v4.f32 {%0,%1,%2,%3}, [%4], %5;"
                 : "=f"(v.x), "=f"(v.y), "=f"(v.z), "=f"(v.w)
                 : "l"(p), "l"(pol));
    return v;
}

__device__ __forceinline__ void stg_stream(float4* p, float4 v) {
    asm volatile("st.global.cs.v4.f32 [%0], {%1,%2,%3,%4};"
                 :: "l"(p), "f"(v.x), "f"(v.y), "f"(v.z), "f"(v.w) : "memory");
}

__device__ __forceinline__ long long ldg_cs64(const long long* p) {
    long long v;
    asm volatile("ld.global.cs.s64 %0, [%1];" : "=l"(v) : "l"(p));
    return v;
}

__device__ __forceinline__ int ldg_cs32(const int* p) {
    int v;
    asm volatile("ld.global.cs.s32 %0, [%1];" : "=r"(v) : "l"(p));
    return v;
}

__global__ __launch_bounds__(256, 4) void gcn_agg_kernel(
    const float4* __restrict__ feat,
    const void*   __restrict__ nodes,
    const void*   __restrict__ neigh,
    float4*       __restrict__ out,
    int B)
{
    const int gwarp = (blockIdx.x * blockDim.x + threadIdx.x) >> 5;
    const int lane  = threadIdx.x & 31;
    if (gwarp >= B) return;

    // Coalesced index fetch: lane j owns neigh[gwarp][j]; self broadcast.
    int my_idx, self_idx;
    if (g_idx_is64) {
        my_idx   = (int)ldg_cs64((const long long*)neigh + (long long)gwarp * KN + lane);
        self_idx = (int)ldg_cs64((const long long*)nodes + gwarp);
    } else {
        my_idx   = ldg_cs32((const int*)neigh + (long long)gwarp * KN + lane);
        self_idx = ldg_cs32((const int*)nodes + gwarp);
    }

    const uint64_t pol = make_keep_policy();

    // 4 independent accumulator chains; 4-wide load groups so the loads
    // within (and across, given 64 regs) groups are batched before any FADD
    // consumes them.
    float4 acc0 = ldg_keep(feat + (long long)self_idx * D4 + lane, pol);
    float4 acc1 = make_float4(0.f, 0.f, 0.f, 0.f);
    float4 acc2 = make_float4(0.f, 0.f, 0.f, 0.f);
    float4 acc3 = make_float4(0.f, 0.f, 0.f, 0.f);

#pragma unroll
    for (int j = 0; j < KN; j += 4) {
        const int i0 = __shfl_sync(0xffffffffu, my_idx, j + 0);
        const int i1 = __shfl_sync(0xffffffffu, my_idx, j + 1);
        const int i2 = __shfl_sync(0xffffffffu, my_idx, j + 2);
        const int i3 = __shfl_sync(0xffffffffu, my_idx, j + 3);
        const float4 v0 = ldg_keep(feat + (long long)i0 * D4 + lane, pol);
        const float4 v1 = ldg_keep(feat + (long long)i1 * D4 + lane, pol);
        const float4 v2 = ldg_keep(feat + (long long)i2 * D4 + lane, pol);
        const float4 v3 = ldg_keep(feat + (long long)i3 * D4 + lane, pol);
        acc0.x += v0.x; acc0.y += v0.y; acc0.z += v0.z; acc0.w += v0.w;
        acc1.x += v1.x; acc1.y += v1.y; acc1.z += v1.z; acc1.w += v1.w;
        acc2.x += v2.x; acc2.y += v2.y; acc2.z += v2.z; acc2.w += v2.w;
        acc3.x += v3.x; acc3.y += v3.y; acc3.z += v3.z; acc3.w += v3.w;
    }

    float4 r;
    r.x = ((acc0.x + acc1.x) + (acc2.x + acc3.x)) * INV_CNT;
    r.y = ((acc0.y + acc1.y) + (acc2.y + acc3.y)) * INV_CNT;
    r.z = ((acc0.z + acc1.z) + (acc2.z + acc3.z)) * INV_CNT;
    r.w = ((acc0.w + acc1.w) + (acc2.w + acc3.w)) * INV_CNT;

    stg_stream(out + (long long)gwarp * D4 + lane, r);
}

extern "C" void kernel_launch(void* const* d_in, const int* in_sizes, int n_in,
                              void* d_out, int out_size) {
    const float4* feat  = (const float4*)d_in[0];
    const void*   nodes = d_in[1];
    const void*   neigh = d_in[2];
    float4*       out   = (float4*)d_out;

    const int B = in_sizes[1];  // 50000

    detect_idx_dtype<<<1, 1>>>((const int*)nodes);

    const int threads = 256;
    const int blocks  = (B * 32 + threads - 1) / threads;
    gcn_agg_kernel<<<blocks, threads>>>(feat, nodes, neigh, out, B);
}